// round 12
// baseline (speedup 1.0000x reference)
#include <cuda_runtime.h>
#include <cuda_bf16.h>
#include <math.h>

#define S   768
#define CS  384
#define CP  128
#define E   16
#define PQ  4
#define PV  8
#define H   12
#define NCOL 1152            // per-residue projection columns: H*96
#define FOUT 2112            // H*(CP+E+PV*4)
#define SPLITK 3

#define SCALE_SINGLE 0.25f   // 1/sqrt(16)
#define SCALE_FRAME (-0.11785113019775793f)   // -1/sqrt(72)

typedef unsigned long long ull;

// packed f32x2 helpers
#define FFMA2(acc, a, b) asm volatile("fma.rn.f32x2 %0, %1, %2, %0;" : "+l"(acc) : "l"(a), "l"(b))
#define PACKDUP(out, x)  asm volatile("mov.b64 %0, {%1, %1};" : "=l"(out) : "f"(x))
#define UNPACK2(lo, hi, v) asm volatile("mov.b64 {%0, %1}, %2;" : "=f"(lo), "=f"(hi) : "l"(v))

// ---------------- scratch ----------------
__device__ float g_raw[S * NCOL];
__device__ float g_Qcat[H * S * 28];
__device__ float g_Kcat[H * S * 28];
__device__ float g_Vcat[H * S * 40];
__device__ float g_qn[H * S];
__device__ float g_kn[H * S];
__device__ float g_a[H * S * S];           // logits -> softmax in place (28.3MB)
__device__ float g_aspart[8][H * S];
__device__ float g_asum[H * S];
__device__ float g_ol[H * S * PV * 3];
__device__ float g_attn[S * FOUT];
__device__ float g_part[SPLITK][S * CS];

// ---------------- kernel 1: projection GEMM ----------------
__device__ __forceinline__ const float* colptr(int j,
    const float* Wq, const float* Wk, const float* Wv,
    const float* Wqp, const float* Wkp, const float* Wvp) {
    int h = j / 96, off = j % 96;
    if (off < 16) return Wq  + (h * 16 + off) * CS;
    if (off < 32) return Wk  + (h * 16 + off - 16) * CS;
    if (off < 48) return Wv  + (h * 16 + off - 32) * CS;
    if (off < 60) return Wqp + (h * 12 + off - 48) * CS;
    if (off < 72) return Wkp + (h * 12 + off - 60) * CS;
    return Wvp + (h * 24 + off - 72) * CS;
}

// grid (96, 2) x 288 threads: 8 s-rows, 576-column half, exactly 2 cols/thread
__global__ void __launch_bounds__(288) k_proj(const float* __restrict__ x,
    const float* __restrict__ Wq, const float* __restrict__ Wk, const float* __restrict__ Wv,
    const float* __restrict__ Wqp, const float* __restrict__ Wkp, const float* __restrict__ Wvp) {
    __shared__ float xs[8 * CS];
    int s0 = blockIdx.x * 8;
    int j0 = blockIdx.y * 576 + threadIdx.x * 2;
    for (int idx = threadIdx.x; idx < 8 * CS; idx += 288)
        xs[idx] = x[s0 * CS + idx];
    __syncthreads();

    const float* w0 = colptr(j0,     Wq, Wk, Wv, Wqp, Wkp, Wvp);
    const float* w1 = colptr(j0 + 1, Wq, Wk, Wv, Wqp, Wkp, Wvp);
    float acc0[8], acc1[8];
    #pragma unroll
    for (int s = 0; s < 8; s++) { acc0[s] = 0.f; acc1[s] = 0.f; }
    for (int kk = 0; kk < CS; kk += 4) {
        float4 wa = *(const float4*)(w0 + kk);
        float4 wb = *(const float4*)(w1 + kk);
        #pragma unroll
        for (int s = 0; s < 8; s++) {
            float4 xv = *(const float4*)&xs[s * CS + kk];
            acc0[s] += wa.x * xv.x + wa.y * xv.y + wa.z * xv.z + wa.w * xv.w;
            acc1[s] += wb.x * xv.x + wb.y * xv.y + wb.z * xv.z + wb.w * xv.w;
        }
    }
    #pragma unroll
    for (int s = 0; s < 8; s++) {
        g_raw[(s0 + s) * NCOL + j0]     = acc0[s];
        g_raw[(s0 + s) * NCOL + j0 + 1] = acc1[s];
    }
}

// ---------------- kernel 2: frame apply + scale folding ----------------
__global__ void k_frames(const float* __restrict__ rot, const float* __restrict__ trans,
                         const float* __restrict__ gamma) {
    int idx = blockIdx.x * blockDim.x + threadIdx.x;
    if (idx >= H * S) return;
    int h = idx / S, s = idx % S;
    const float* R = rot + s * 9;
    float R00=R[0],R01=R[1],R02=R[2],R10=R[3],R11=R[4],R12=R[5],R20=R[6],R21=R[7],R22=R[8];
    float t0 = trans[s*3+0], t1 = trans[s*3+1], t2 = trans[s*3+2];
    float ch = SCALE_FRAME * log1pf(expf(gamma[h]));

    const float* raw = g_raw + s * NCOL + h * 96;
    float* qc = g_Qcat + (h * S + s) * 28;
    float* kc = g_Kcat + (h * S + s) * 28;
    float* vc = g_Vcat + (h * S + s) * 40;

    #pragma unroll
    for (int e = 0; e < 16; e++) {
        qc[e] = raw[e] * SCALE_SINGLE;
        kc[e] = raw[16 + e];
        vc[e] = raw[32 + e];
    }
    float qn = 0.f, kn = 0.f;
    float m2c = -2.f * ch;
    #pragma unroll
    for (int p = 0; p < 4; p++) {
        float x = raw[48+p*3], y = raw[48+p*3+1], z = raw[48+p*3+2];
        float lx = R00*x + R01*y + R02*z + t0;
        float ly = R10*x + R11*y + R12*z + t1;
        float lz = R20*x + R21*y + R22*z + t2;
        qc[16+p*3]   = lx * m2c;
        qc[16+p*3+1] = ly * m2c;
        qc[16+p*3+2] = lz * m2c;
        qn += lx*lx + ly*ly + lz*lz;

        x = raw[60+p*3]; y = raw[60+p*3+1]; z = raw[60+p*3+2];
        lx = R00*x + R01*y + R02*z + t0;
        ly = R10*x + R11*y + R12*z + t1;
        lz = R20*x + R21*y + R22*z + t2;
        kc[16+p*3]   = lx;
        kc[16+p*3+1] = ly;
        kc[16+p*3+2] = lz;
        kn += lx*lx + ly*ly + lz*lz;
    }
    #pragma unroll
    for (int p = 0; p < 8; p++) {
        float x = raw[72+p*3], y = raw[72+p*3+1], z = raw[72+p*3+2];
        vc[16+p*3]   = R00*x + R01*y + R02*z + t0;
        vc[16+p*3+1] = R10*x + R11*y + R12*z + t1;
        vc[16+p*3+2] = R20*x + R21*y + R22*z + t2;
    }
    g_qn[h * S + s] = ch * qn;
    g_kn[h * S + s] = ch * kn;
}

// ---------------- kernel 3: batched logit GEMM (K=28) ----------------
__global__ void __launch_bounds__(256) k_logit() {
    __shared__ float Qs[64 * 29], Ks[64 * 29], qns[64], kns[64];
    int h = blockIdx.z, i0 = blockIdx.y * 64, j0 = blockIdx.x * 64;
    int t = threadIdx.x;
    for (int idx = t; idx < 64 * 28; idx += 256) {
        int r = idx / 28, c = idx % 28;
        Qs[r * 29 + c] = g_Qcat[(h * S + i0 + r) * 28 + c];
        Ks[r * 29 + c] = g_Kcat[(h * S + j0 + r) * 28 + c];
    }
    if (t < 64) { qns[t] = g_qn[h * S + i0 + t]; kns[t] = g_kn[h * S + j0 + t]; }
    __syncthreads();
    int tx = t % 16, ty = t / 16;
    float acc[4][4] = {};
    for (int k = 0; k < 28; k++) {
        float aq[4], bk[4];
        #pragma unroll
        for (int r = 0; r < 4; r++) {
            aq[r] = Qs[(ty * 4 + r) * 29 + k];
            bk[r] = Ks[(tx * 4 + r) * 29 + k];
        }
        #pragma unroll
        for (int r = 0; r < 4; r++)
            #pragma unroll
            for (int c = 0; c < 4; c++)
                acc[r][c] += aq[r] * bk[c];
    }
    #pragma unroll
    for (int r = 0; r < 4; r++)
        #pragma unroll
        for (int c = 0; c < 4; c++)
            g_a[((size_t)h * S + i0 + ty * 4 + r) * S + j0 + tx * 4 + c] =
                acc[r][c] + qns[ty * 4 + r] + kns[tx * 4 + c];
}

// ---------------- kernel 4: FUSED w_pair + softmax (block per query row i) --------
// 384 threads. Phase A: wp[h][j] = Wb[h].pair[i,j,:] for all 768 j into smem
// (each thread owns j = {t*2? no: idx>>1 mapping}, c-chunks of 8, pipelined).
// Phase B: 12 warps do the per-head softmax directly (adds wp from smem).
__global__ void __launch_bounds__(384) k_wpairsm(const float* __restrict__ pair,
                                                 const float* __restrict__ Wb) {
    __shared__ float ps[S * 12];        // [j][8c] padded to 12 floats/row (36KB)
    __shared__ float wps[H * 772];      // wp [h][j], row stride 772 (36.2KB)
    __shared__ float wbs[H * CP];       // full Wb (6KB)
    int i = blockIdx.x, t = threadIdx.x;

    for (int idx = t; idx < H * CP; idx += 384) wbs[idx] = Wb[idx];

    const float4* pair4 = (const float4*)pair;
    int j1 = t, j2 = t + 384;           // this thread's two j rows

    // prefetch chunk 0: idx = t + l*384 -> j = idx>>1, c4 = idx&1
    float4 regs[4];
    #pragma unroll
    for (int l = 0; l < 4; l++) {
        int idx = t + l * 384;
        regs[l] = pair4[((size_t)i * S + (idx >> 1)) * 32 + (idx & 1)];
    }

    ull acc[2][12] = {};
    for (int cc = 0; cc < 16; cc++) {
        __syncthreads();
        #pragma unroll
        for (int l = 0; l < 4; l++) {
            int idx = t + l * 384;
            *(float4*)&ps[(idx >> 1) * 12 + (idx & 1) * 4] = regs[l];
        }
        if (cc < 15) {
            #pragma unroll
            for (int l = 0; l < 4; l++) {
                int idx = t + l * 384;
                regs[l] = pair4[((size_t)i * S + (idx >> 1)) * 32 + (cc + 1) * 2 + (idx & 1)];
            }
        }
        __syncthreads();
        #pragma unroll
        for (int c4 = 0; c4 < 2; c4++) {
            ulonglong2 pa = *(const ulonglong2*)&ps[j1 * 12 + c4 * 4];
            ulonglong2 pb = *(const ulonglong2*)&ps[j2 * 12 + c4 * 4];
            #pragma unroll
            for (int h = 0; h < 12; h++) {
                ulonglong2 wb = *(const ulonglong2*)&wbs[h * CP + cc * 8 + c4 * 4];
                FFMA2(acc[0][h], pa.x, wb.x);
                FFMA2(acc[0][h], pa.y, wb.y);
                FFMA2(acc[1][h], pb.x, wb.x);
                FFMA2(acc[1][h], pb.y, wb.y);
            }
        }
    }
    #pragma unroll
    for (int h = 0; h < 12; h++) {
        float lo, hi;
        UNPACK2(lo, hi, acc[0][h]);
        wps[h * 772 + j1] = lo + hi;
        UNPACK2(lo, hi, acc[1][h]);
        wps[h * 772 + j2] = lo + hi;
    }
    __syncthreads();

    // ---- phase B: softmax, warp per head ----
    int lane = t & 31, h = t >> 5;
    float4* row = (float4*)(g_a + ((size_t)h * S + i) * S);
    const float4* wp4 = (const float4*)&wps[h * 772];

    float4 v[6];
    float m = -1e30f;
    #pragma unroll
    for (int r = 0; r < 6; r++) {
        float4 a = row[r * 32 + lane];
        float4 w = wp4[r * 32 + lane];
        v[r].x = a.x + w.x; v[r].y = a.y + w.y;
        v[r].z = a.z + w.z; v[r].w = a.w + w.w;
        m = fmaxf(m, fmaxf(fmaxf(v[r].x, v[r].y), fmaxf(v[r].z, v[r].w)));
    }
    #pragma unroll
    for (int off = 16; off; off >>= 1) m = fmaxf(m, __shfl_xor_sync(0xffffffffu, m, off));
    float sum = 0.f;
    #pragma unroll
    for (int r = 0; r < 6; r++) {
        v[r].x = __expf(v[r].x - m); v[r].y = __expf(v[r].y - m);
        v[r].z = __expf(v[r].z - m); v[r].w = __expf(v[r].w - m);
        sum += (v[r].x + v[r].y) + (v[r].z + v[r].w);
    }
    #pragma unroll
    for (int off = 16; off; off >>= 1) sum += __shfl_xor_sync(0xffffffffu, sum, off);
    float inv = 1.f / sum;
    #pragma unroll
    for (int r = 0; r < 6; r++) {
        v[r].x *= inv; v[r].y *= inv; v[r].z *= inv; v[r].w *= inv;
        row[r * 32 + lane] = v[r];
    }
}

// ---------------- kernel 5: a_sum partials over i (8 splits) ----------------
__global__ void __launch_bounds__(256) k_asum() {
    int h = blockIdx.y, z = blockIdx.z;
    int k = blockIdx.x * 256 + threadIdx.x;
    const float* base = g_a + (size_t)h * S * S + (size_t)z * 96 * S + k;
    float s0 = 0.f, s1 = 0.f, s2 = 0.f, s3 = 0.f;
    for (int i = 0; i < 96; i += 4) {
        s0 += base[(size_t)(i + 0) * S];
        s1 += base[(size_t)(i + 1) * S];
        s2 += base[(size_t)(i + 2) * S];
        s3 += base[(size_t)(i + 3) * S];
    }
    g_aspart[z][h * S + k] = (s0 + s1) + (s2 + s3);
}

__global__ void __launch_bounds__(256) k_asred() {
    int idx = blockIdx.x * 256 + threadIdx.x;    // H*S = 9216
    float s = 0.f;
    #pragma unroll
    for (int z = 0; z < 8; z++) s += g_aspart[z][idx];
    g_asum[idx] = s;
}

// ---------------- kernel 6: per-head A @ Vcat (256 threads) ----------------
__global__ void __launch_bounds__(256) k_av() {
    __shared__ float As[64 * 65];
    __shared__ float Vs[64 * 41];
    int h = blockIdx.y, i0 = blockIdx.x * 64;
    int t = threadIdx.x;
    int ig = t >> 3, ng = t & 7;     // 32 i-pairs x 8 n-groups
    float acc[2][5] = {};

    for (int kc = 0; kc < S; kc += 64) {
        __syncthreads();
        for (int idx = t; idx < 64 * 64; idx += 256) {
            int r = idx >> 6, k = idx & 63;
            As[r * 65 + k] = g_a[((size_t)h * S + i0 + r) * S + kc + k];
        }
        for (int idx = t; idx < 64 * 40; idx += 256) {
            int r = idx / 40, n = idx % 40;
            Vs[r * 41 + n] = g_Vcat[(h * S + kc + r) * 40 + n];
        }
        __syncthreads();
        #pragma unroll 4
        for (int k = 0; k < 64; k++) {
            float a0 = As[(2 * ig) * 65 + k], a1 = As[(2 * ig + 1) * 65 + k];
            float vv[5];
            #pragma unroll
            for (int c = 0; c < 5; c++) vv[c] = Vs[k * 41 + ng + 8 * c];
            #pragma unroll
            for (int c = 0; c < 5; c++) {
                acc[0][c] += a0 * vv[c];
                acc[1][c] += a1 * vv[c];
            }
        }
    }
    #pragma unroll
    for (int r = 0; r < 2; r++) {
        int i = i0 + 2 * ig + r;
        #pragma unroll
        for (int c = 0; c < 5; c++) {
            int n = ng + 8 * c;
            float val = acc[r][c];
            if (n < 16) g_attn[i * FOUT + h * 16 + n] = val;
            else        g_ol[(h * S + i) * 24 + (n - 16)] = val;
        }
    }
}

// ---------------- kernel 7: inverse frame, points + norms ----------------
__global__ void k_invf(const float* __restrict__ rot, const float* __restrict__ trans) {
    int idx = blockIdx.x * blockDim.x + threadIdx.x;
    if (idx >= H * S) return;
    int h = idx / S, s = idx % S;
    const float* R = rot + s * 9;
    float R00=R[0],R01=R[1],R02=R[2],R10=R[3],R11=R[4],R12=R[5],R20=R[6],R21=R[7],R22=R[8];
    float t0 = trans[s*3+0], t1 = trans[s*3+1], t2 = trans[s*3+2];
    const float* ol = g_ol + (h * S + s) * 24;
    float* dst = g_attn + s * FOUT;
    #pragma unroll
    for (int p = 0; p < PV; p++) {
        float x = ol[p*3+0] - t0, y = ol[p*3+1] - t1, z = ol[p*3+2] - t2;
        float gx = R00*x + R10*y + R20*z;
        float gy = R01*x + R11*y + R21*z;
        float gz = R02*x + R12*y + R22*z;
        dst[1728 + p*36 + h*3 + 0] = gx;
        dst[1728 + p*36 + h*3 + 1] = gy;
        dst[1728 + p*36 + h*3 + 2] = gz;
        dst[2016 + p*12 + h] = sqrtf(gx*gx + gy*gy + gz*gz);
    }
}

// ---------------- kernel 8: o_pair, double-buffered second pair pass ----------------
__global__ void __launch_bounds__(256) k_opair(const float* __restrict__ pair) {
    __shared__ float ps[2][2 * 32 * 128];   // ping-pong [i][k][c] (64KB)
    __shared__ ull   asumP[2][12 * 32];     // packed {a,a} per (h,k) (6KB)
    int i0 = blockIdx.x * 2;
    int t = threadIdx.x;
    int il = t >> 7;                 // 0/1 (uniform within warp)
    int cg = ((t >> 2) & 31) * 4;    // c base (4 consecutive)
    int h0 = (t & 3) * 3;            // 3 heads

    const float4* pair4 = (const float4*)pair;
    float4 regs[8];
    float aregs[2];
    #pragma unroll
    for (int l = 0; l < 8; l++) {
        int idx = t + l * 256;
        int ii = idx >> 10, rem = idx & 1023;
        regs[l] = pair4[((size_t)(i0 + ii) * S + (rem >> 5)) * 32 + (rem & 31)];
    }
    #pragma unroll
    for (int l = 0; l < 2; l++) {
        int idx = t + l * 256;
        aregs[l] = (idx < 384) ? g_asum[(idx >> 5) * S + (idx & 31)] : 0.f;
    }

    ull acc[3][2] = {};
    for (int kc = 0; kc < 24; kc++) {
        int buf = kc & 1;
        __syncthreads();
        #pragma unroll
        for (int l = 0; l < 8; l++) {
            int idx = t + l * 256;
            int ii = idx >> 10, rem = idx & 1023;
            *(float4*)&ps[buf][(ii * 32 + (rem >> 5)) * 128 + (rem & 31) * 4] = regs[l];
        }
        #pragma unroll
        for (int l = 0; l < 2; l++) {
            int idx = t + l * 256;
            if (idx < 384) { ull ad; PACKDUP(ad, aregs[l]); asumP[buf][idx] = ad; }
        }
        if (kc < 23) {
            int k0 = (kc + 1) * 32;
            #pragma unroll
            for (int l = 0; l < 8; l++) {
                int idx = t + l * 256;
                int ii = idx >> 10, rem = idx & 1023;
                regs[l] = pair4[((size_t)(i0 + ii) * S + k0 + (rem >> 5)) * 32 + (rem & 31)];
            }
            #pragma unroll
            for (int l = 0; l < 2; l++) {
                int idx = t + l * 256;
                if (idx < 384) aregs[l] = g_asum[(idx >> 5) * S + k0 + (idx & 31)];
            }
        }
        __syncthreads();
        #pragma unroll
        for (int k = 0; k < 32; k++) {
            ulonglong2 p = *(const ulonglong2*)&ps[buf][(il * 32 + k) * 128 + cg];
            ull a0 = asumP[buf][h0 * 32 + k];
            ull a1 = asumP[buf][(h0 + 1) * 32 + k];
            ull a2 = asumP[buf][(h0 + 2) * 32 + k];
            FFMA2(acc[0][0], p.x, a0); FFMA2(acc[0][1], p.y, a0);
            FFMA2(acc[1][0], p.x, a1); FFMA2(acc[1][1], p.y, a1);
            FFMA2(acc[2][0], p.x, a2); FFMA2(acc[2][1], p.y, a2);
        }
    }
    int i = i0 + il;
    #pragma unroll
    for (int hh = 0; hh < 3; hh++) {
        float4 o;
        UNPACK2(o.x, o.y, acc[hh][0]);
        UNPACK2(o.z, o.w, acc[hh][1]);
        *(float4*)&g_attn[i * FOUT + 192 + (h0 + hh) * CP + cg] = o;
    }
}

// ---------------- kernel 9: split-K final GEMM -> partials ----------------
__global__ void __launch_bounds__(256) k_out(const float* __restrict__ Wo) {
    __shared__ float As[32 * 68];   // [kk][m]
    __shared__ float Bs[32 * 68];   // [kk][n]
    int i0 = blockIdx.x * 64, n0 = blockIdx.y * 64;
    int kb = blockIdx.z * (FOUT / SPLITK);
    int ke = kb + (FOUT / SPLITK);
    int t = threadIdx.x, tx = t % 16, ty = t / 16;
    ull acc[4][2] = {};
    for (int kc = kb; kc < ke; kc += 32) {
        __syncthreads();
        for (int idx = t; idx < 64 * 32; idx += 256) {
            int m = idx >> 5, kk = idx & 31;
            As[kk * 68 + m] = g_attn[(i0 + m) * FOUT + kc + kk];
            Bs[kk * 68 + m] = Wo[(n0 + m) * FOUT + kc + kk];
        }
        __syncthreads();
        #pragma unroll 4
        for (int kk = 0; kk < 32; kk++) {
            float4 am = *(const float4*)&As[kk * 68 + ty * 4];
            ulonglong2 bp = *(const ulonglong2*)&Bs[kk * 68 + tx * 4];
            ull a0, a1, a2, a3;
            PACKDUP(a0, am.x); PACKDUP(a1, am.y); PACKDUP(a2, am.z); PACKDUP(a3, am.w);
            FFMA2(acc[0][0], a0, bp.x); FFMA2(acc[0][1], a0, bp.y);
            FFMA2(acc[1][0], a1, bp.x); FFMA2(acc[1][1], a1, bp.y);
            FFMA2(acc[2][0], a2, bp.x); FFMA2(acc[2][1], a2, bp.y);
            FFMA2(acc[3][0], a3, bp.x); FFMA2(acc[3][1], a3, bp.y);
        }
    }
    float* dst = g_part[blockIdx.z];
    #pragma unroll
    for (int r = 0; r < 4; r++) {
        float4 o;
        UNPACK2(o.x, o.y, acc[r][0]);
        UNPACK2(o.z, o.w, acc[r][1]);
        *(float4*)&dst[(i0 + ty * 4 + r) * CS + n0 + tx * 4] = o;
    }
}

__global__ void __launch_bounds__(256) k_fin(const float* __restrict__ bo,
                                             float* __restrict__ out) {
    int idx = blockIdx.x * 256 + threadIdx.x;   // 294912 elems
    int n = idx % CS;
    out[idx] = bo[n] + g_part[0][idx] + g_part[1][idx] + g_part[2][idx];
}

// ---------------- launch (single stream — streams measured as a regression) ------
extern "C" void kernel_launch(void* const* d_in, const int* in_sizes, int n_in,
                              void* d_out, int out_size) {
    const float* single = (const float*)d_in[0];
    const float* pair   = (const float*)d_in[1];
    const float* rot    = (const float*)d_in[2];
    const float* trans  = (const float*)d_in[3];
    const float* Wq     = (const float*)d_in[4];
    const float* Wk     = (const float*)d_in[5];
    const float* Wv     = (const float*)d_in[6];
    const float* Wqp    = (const float*)d_in[7];
    const float* Wkp    = (const float*)d_in[8];
    const float* Wvp    = (const float*)d_in[9];
    const float* Wb     = (const float*)d_in[10];
    const float* Wo     = (const float*)d_in[11];
    const float* bo     = (const float*)d_in[12];
    const float* gamma  = (const float*)d_in[13];
    float* out = (float*)d_out;

    k_proj<<<dim3(S / 8, 2), 288>>>(single, Wq, Wk, Wv, Wqp, Wkp, Wvp);
    k_frames<<<(H * S + 255) / 256, 256>>>(rot, trans, gamma);
    k_logit<<<dim3(S / 64, S / 64, H), 256>>>();
    k_wpairsm<<<S, 384>>>(pair, Wb);
    k_asum<<<dim3(S / 256, H, 8), 256>>>();
    k_asred<<<(H * S) / 256, 256>>>();
    k_av<<<dim3(S / 64, H), 256>>>();
    k_invf<<<(H * S + 255) / 256, 256>>>(rot, trans);
    k_opair<<<S / 2, 256>>>(pair);
    k_out<<<dim3(S / 64, CS / 64, SPLITK), 256>>>(Wo);
    k_fin<<<(S * CS) / 256, 256>>>(bo, out);
}

// round 14
// speedup vs baseline: 1.0320x; 1.0320x over previous
#include <cuda_runtime.h>
#include <cuda_bf16.h>
#include <math.h>

#define S   768
#define CS  384
#define CP  128
#define E   16
#define PQ  4
#define PV  8
#define H   12
#define NCOL 1152            // per-residue projection columns: H*96
#define FOUT 2112            // H*(CP+E+PV*4)
#define SPLITK 3

#define SCALE_SINGLE 0.25f   // 1/sqrt(16)
#define SCALE_FRAME (-0.11785113019775793f)   // -1/sqrt(72)

typedef unsigned long long ull;

// packed f32x2 helpers
#define FFMA2(acc, a, b) asm volatile("fma.rn.f32x2 %0, %1, %2, %0;" : "+l"(acc) : "l"(a), "l"(b))
#define PACKDUP(out, x)  asm volatile("mov.b64 %0, {%1, %1};" : "=l"(out) : "f"(x))
#define UNPACK2(lo, hi, v) asm volatile("mov.b64 {%0, %1}, %2;" : "=f"(lo), "=f"(hi) : "l"(v))

// ---------------- scratch ----------------
__device__ float g_raw[S * NCOL];
__device__ float g_Qcat[H * S * 28];
__device__ float g_Kcat[H * S * 28];
__device__ float g_Vcat[H * S * 40];
__device__ float g_qn[H * S];
__device__ float g_kn[H * S];
__device__ float g_a[H * S * S];           // logits -> softmax in place (28.3MB)
__device__ float g_wp[S * H * S];          // pair bias [i][h][j] (28.3MB)
__device__ float g_aspart[8][H * S];
__device__ float g_asum[H * S];
__device__ float g_ol[H * S * PV * 3];
__device__ float g_attn[S * FOUT];
__device__ float g_part[SPLITK][S * CS];

// ---------------- kernel 1: projection GEMM ----------------
__device__ __forceinline__ const float* colptr(int j,
    const float* Wq, const float* Wk, const float* Wv,
    const float* Wqp, const float* Wkp, const float* Wvp) {
    int h = j / 96, off = j % 96;
    if (off < 16) return Wq  + (h * 16 + off) * CS;
    if (off < 32) return Wk  + (h * 16 + off - 16) * CS;
    if (off < 48) return Wv  + (h * 16 + off - 32) * CS;
    if (off < 60) return Wqp + (h * 12 + off - 48) * CS;
    if (off < 72) return Wkp + (h * 12 + off - 60) * CS;
    return Wvp + (h * 24 + off - 72) * CS;
}

// grid (96, 2) x 288 threads: 8 s-rows, 576-column half, exactly 2 cols/thread
__global__ void __launch_bounds__(288) k_proj(const float* __restrict__ x,
    const float* __restrict__ Wq, const float* __restrict__ Wk, const float* __restrict__ Wv,
    const float* __restrict__ Wqp, const float* __restrict__ Wkp, const float* __restrict__ Wvp) {
    __shared__ float xs[8 * CS];
    int s0 = blockIdx.x * 8;
    int j0 = blockIdx.y * 576 + threadIdx.x * 2;
    for (int idx = threadIdx.x; idx < 8 * CS; idx += 288)
        xs[idx] = x[s0 * CS + idx];
    __syncthreads();

    const float* w0 = colptr(j0,     Wq, Wk, Wv, Wqp, Wkp, Wvp);
    const float* w1 = colptr(j0 + 1, Wq, Wk, Wv, Wqp, Wkp, Wvp);
    float acc0[8], acc1[8];
    #pragma unroll
    for (int s = 0; s < 8; s++) { acc0[s] = 0.f; acc1[s] = 0.f; }
    for (int kk = 0; kk < CS; kk += 4) {
        float4 wa = *(const float4*)(w0 + kk);
        float4 wb = *(const float4*)(w1 + kk);
        #pragma unroll
        for (int s = 0; s < 8; s++) {
            float4 xv = *(const float4*)&xs[s * CS + kk];
            acc0[s] += wa.x * xv.x + wa.y * xv.y + wa.z * xv.z + wa.w * xv.w;
            acc1[s] += wb.x * xv.x + wb.y * xv.y + wb.z * xv.z + wb.w * xv.w;
        }
    }
    #pragma unroll
    for (int s = 0; s < 8; s++) {
        g_raw[(s0 + s) * NCOL + j0]     = acc0[s];
        g_raw[(s0 + s) * NCOL + j0 + 1] = acc1[s];
    }
}

// ---------------- kernel 2: frame apply + scale folding ----------------
__global__ void k_frames(const float* __restrict__ rot, const float* __restrict__ trans,
                         const float* __restrict__ gamma) {
    int idx = blockIdx.x * blockDim.x + threadIdx.x;
    if (idx >= H * S) return;
    int h = idx / S, s = idx % S;
    const float* R = rot + s * 9;
    float R00=R[0],R01=R[1],R02=R[2],R10=R[3],R11=R[4],R12=R[5],R20=R[6],R21=R[7],R22=R[8];
    float t0 = trans[s*3+0], t1 = trans[s*3+1], t2 = trans[s*3+2];
    float ch = SCALE_FRAME * log1pf(expf(gamma[h]));

    const float* raw = g_raw + s * NCOL + h * 96;
    float* qc = g_Qcat + (h * S + s) * 28;
    float* kc = g_Kcat + (h * S + s) * 28;
    float* vc = g_Vcat + (h * S + s) * 40;

    #pragma unroll
    for (int e = 0; e < 16; e++) {
        qc[e] = raw[e] * SCALE_SINGLE;
        kc[e] = raw[16 + e];
        vc[e] = raw[32 + e];
    }
    float qn = 0.f, kn = 0.f;
    float m2c = -2.f * ch;
    #pragma unroll
    for (int p = 0; p < 4; p++) {
        float x = raw[48+p*3], y = raw[48+p*3+1], z = raw[48+p*3+2];
        float lx = R00*x + R01*y + R02*z + t0;
        float ly = R10*x + R11*y + R12*z + t1;
        float lz = R20*x + R21*y + R22*z + t2;
        qc[16+p*3]   = lx * m2c;
        qc[16+p*3+1] = ly * m2c;
        qc[16+p*3+2] = lz * m2c;
        qn += lx*lx + ly*ly + lz*lz;

        x = raw[60+p*3]; y = raw[60+p*3+1]; z = raw[60+p*3+2];
        lx = R00*x + R01*y + R02*z + t0;
        ly = R10*x + R11*y + R12*z + t1;
        lz = R20*x + R21*y + R22*z + t2;
        kc[16+p*3]   = lx;
        kc[16+p*3+1] = ly;
        kc[16+p*3+2] = lz;
        kn += lx*lx + ly*ly + lz*lz;
    }
    #pragma unroll
    for (int p = 0; p < 8; p++) {
        float x = raw[72+p*3], y = raw[72+p*3+1], z = raw[72+p*3+2];
        vc[16+p*3]   = R00*x + R01*y + R02*z + t0;
        vc[16+p*3+1] = R10*x + R11*y + R12*z + t1;
        vc[16+p*3+2] = R20*x + R21*y + R22*z + t2;
    }
    g_qn[h * S + s] = ch * qn;
    g_kn[h * S + s] = ch * kn;
}

// ---------------- kernel 3: batched logit GEMM (K=28) ----------------
__global__ void __launch_bounds__(256) k_logit() {
    __shared__ float Qs[64 * 29], Ks[64 * 29], qns[64], kns[64];
    int h = blockIdx.z, i0 = blockIdx.y * 64, j0 = blockIdx.x * 64;
    int t = threadIdx.x;
    for (int idx = t; idx < 64 * 28; idx += 256) {
        int r = idx / 28, c = idx % 28;
        Qs[r * 29 + c] = g_Qcat[(h * S + i0 + r) * 28 + c];
        Ks[r * 29 + c] = g_Kcat[(h * S + j0 + r) * 28 + c];
    }
    if (t < 64) { qns[t] = g_qn[h * S + i0 + t]; kns[t] = g_kn[h * S + j0 + t]; }
    __syncthreads();
    int tx = t % 16, ty = t / 16;
    float acc[4][4] = {};
    for (int k = 0; k < 28; k++) {
        float aq[4], bk[4];
        #pragma unroll
        for (int r = 0; r < 4; r++) {
            aq[r] = Qs[(ty * 4 + r) * 29 + k];
            bk[r] = Ks[(tx * 4 + r) * 29 + k];
        }
        #pragma unroll
        for (int r = 0; r < 4; r++)
            #pragma unroll
            for (int c = 0; c < 4; c++)
                acc[r][c] += aq[r] * bk[c];
    }
    #pragma unroll
    for (int r = 0; r < 4; r++)
        #pragma unroll
        for (int c = 0; c < 4; c++)
            g_a[((size_t)h * S + i0 + ty * 4 + r) * S + j0 + tx * 4 + c] =
                acc[r][c] + qns[ty * 4 + r] + kns[tx * 4 + c];
}

// ---------------- kernel 4a: wp[i][h][j] = Wb[h] . pair[i,j,:] ----------------
// One j per thread; swizzled 128B-row pair tile; Wb via LDS broadcast; K-paired f32x2.
__global__ void __launch_bounds__(256) k_wpair(const float* __restrict__ pair,
                                               const float* __restrict__ Wb) {
    __shared__ float ps[256 * 32];      // [j][32c] swizzled in 16B blocks (32KB)
    __shared__ float wbs[12 * 32];      // Wb chunk [h][32c]
    int i = blockIdx.x, j0 = blockIdx.y * 256;
    int t = threadIdx.x;

    ull acc[12] = {};
    const float4* pair4 = (const float4*)pair;

    for (int c0 = 0; c0 < 128; c0 += 32) {
        __syncthreads();
        #pragma unroll
        for (int l = 0; l < 8; l++) {
            int idx = t + l * 256;            // 2048 float4
            int j = idx >> 3, c4 = idx & 7;
            float4 v = pair4[((size_t)i * S + j0 + j) * 32 + (c0 >> 2) + c4];
            int blk = j * 8 + (c4 ^ (j & 7));
            *(float4*)&ps[blk * 4] = v;
        }
        for (int idx = t; idx < 384; idx += 256)
            wbs[idx] = Wb[(idx >> 5) * CP + c0 + (idx & 31)];
        __syncthreads();

        #pragma unroll
        for (int c4 = 0; c4 < 8; c4++) {
            int blk = t * 8 + (c4 ^ (t & 7));
            ulonglong2 pv = *(const ulonglong2*)&ps[blk * 4];
            #pragma unroll
            for (int h = 0; h < 12; h++) {
                ulonglong2 wb = *(const ulonglong2*)&wbs[h * 32 + c4 * 4];
                FFMA2(acc[h], pv.x, wb.x);
                FFMA2(acc[h], pv.y, wb.y);
            }
        }
    }
    #pragma unroll
    for (int h = 0; h < 12; h++) {
        float lo, hi; UNPACK2(lo, hi, acc[h]);
        g_wp[((size_t)i * H + h) * S + j0 + t] = lo + hi;
    }
}

// ---------------- kernel 4b: softmax over j (adds wp), warp per (head,row) --------
// No smem, no block sync: both g_a row and g_wp row are contiguous.
__global__ void __launch_bounds__(384) k_softmax() {
    int i = blockIdx.x, lane = threadIdx.x & 31, h = threadIdx.x >> 5;

    float4* row = (float4*)(g_a + ((size_t)h * S + i) * S);
    const float4* wr = (const float4*)(g_wp + ((size_t)i * H + h) * S);

    float4 v[6];
    float m = -1e30f;
    #pragma unroll
    for (int r = 0; r < 6; r++) {
        float4 a = row[r * 32 + lane];
        float4 w = wr[r * 32 + lane];
        v[r].x = a.x + w.x; v[r].y = a.y + w.y;
        v[r].z = a.z + w.z; v[r].w = a.w + w.w;
        m = fmaxf(m, fmaxf(fmaxf(v[r].x, v[r].y), fmaxf(v[r].z, v[r].w)));
    }
    #pragma unroll
    for (int off = 16; off; off >>= 1) m = fmaxf(m, __shfl_xor_sync(0xffffffffu, m, off));
    float sum = 0.f;
    #pragma unroll
    for (int r = 0; r < 6; r++) {
        v[r].x = __expf(v[r].x - m); v[r].y = __expf(v[r].y - m);
        v[r].z = __expf(v[r].z - m); v[r].w = __expf(v[r].w - m);
        sum += (v[r].x + v[r].y) + (v[r].z + v[r].w);
    }
    #pragma unroll
    for (int off = 16; off; off >>= 1) sum += __shfl_xor_sync(0xffffffffu, sum, off);
    float inv = 1.f / sum;
    #pragma unroll
    for (int r = 0; r < 6; r++) {
        v[r].x *= inv; v[r].y *= inv; v[r].z *= inv; v[r].w *= inv;
        row[r * 32 + lane] = v[r];
    }
}

// ---------------- kernel 5: a_sum partials over i (8 splits) ----------------
__global__ void __launch_bounds__(256) k_asum() {
    int h = blockIdx.y, z = blockIdx.z;
    int k = blockIdx.x * 256 + threadIdx.x;
    const float* base = g_a + (size_t)h * S * S + (size_t)z * 96 * S + k;
    float s0 = 0.f, s1 = 0.f, s2 = 0.f, s3 = 0.f;
    for (int i = 0; i < 96; i += 4) {
        s0 += base[(size_t)(i + 0) * S];
        s1 += base[(size_t)(i + 1) * S];
        s2 += base[(size_t)(i + 2) * S];
        s3 += base[(size_t)(i + 3) * S];
    }
    g_aspart[z][h * S + k] = (s0 + s1) + (s2 + s3);
}

__global__ void __launch_bounds__(256) k_asred() {
    int idx = blockIdx.x * 256 + threadIdx.x;    // H*S = 9216
    float s = 0.f;
    #pragma unroll
    for (int z = 0; z < 8; z++) s += g_aspart[z][idx];
    g_asum[idx] = s;
}

// ---------------- kernel 6: per-head A @ Vcat (256 threads) ----------------
__global__ void __launch_bounds__(256) k_av() {
    __shared__ float As[64 * 65];
    __shared__ float Vs[64 * 41];
    int h = blockIdx.y, i0 = blockIdx.x * 64;
    int t = threadIdx.x;
    int ig = t >> 3, ng = t & 7;     // 32 i-pairs x 8 n-groups
    float acc[2][5] = {};

    for (int kc = 0; kc < S; kc += 64) {
        __syncthreads();
        for (int idx = t; idx < 64 * 64; idx += 256) {
            int r = idx >> 6, k = idx & 63;
            As[r * 65 + k] = g_a[((size_t)h * S + i0 + r) * S + kc + k];
        }
        for (int idx = t; idx < 64 * 40; idx += 256) {
            int r = idx / 40, n = idx % 40;
            Vs[r * 41 + n] = g_Vcat[(h * S + kc + r) * 40 + n];
        }
        __syncthreads();
        #pragma unroll 4
        for (int k = 0; k < 64; k++) {
            float a0 = As[(2 * ig) * 65 + k], a1 = As[(2 * ig + 1) * 65 + k];
            float vv[5];
            #pragma unroll
            for (int c = 0; c < 5; c++) vv[c] = Vs[k * 41 + ng + 8 * c];
            #pragma unroll
            for (int c = 0; c < 5; c++) {
                acc[0][c] += a0 * vv[c];
                acc[1][c] += a1 * vv[c];
            }
        }
    }
    #pragma unroll
    for (int r = 0; r < 2; r++) {
        int i = i0 + 2 * ig + r;
        #pragma unroll
        for (int c = 0; c < 5; c++) {
            int n = ng + 8 * c;
            float val = acc[r][c];
            if (n < 16) g_attn[i * FOUT + h * 16 + n] = val;
            else        g_ol[(h * S + i) * 24 + (n - 16)] = val;
        }
    }
}

// ---------------- kernel 7: inverse frame, points + norms ----------------
__global__ void k_invf(const float* __restrict__ rot, const float* __restrict__ trans) {
    int idx = blockIdx.x * blockDim.x + threadIdx.x;
    if (idx >= H * S) return;
    int h = idx / S, s = idx % S;
    const float* R = rot + s * 9;
    float R00=R[0],R01=R[1],R02=R[2],R10=R[3],R11=R[4],R12=R[5],R20=R[6],R21=R[7],R22=R[8];
    float t0 = trans[s*3+0], t1 = trans[s*3+1], t2 = trans[s*3+2];
    const float* ol = g_ol + (h * S + s) * 24;
    float* dst = g_attn + s * FOUT;
    #pragma unroll
    for (int p = 0; p < PV; p++) {
        float x = ol[p*3+0] - t0, y = ol[p*3+1] - t1, z = ol[p*3+2] - t2;
        float gx = R00*x + R10*y + R20*z;
        float gy = R01*x + R11*y + R21*z;
        float gz = R02*x + R12*y + R22*z;
        dst[1728 + p*36 + h*3 + 0] = gx;
        dst[1728 + p*36 + h*3 + 1] = gy;
        dst[1728 + p*36 + h*3 + 2] = gz;
        dst[2016 + p*12 + h] = sqrtf(gx*gx + gy*gy + gz*gz);
    }
}

// ---------------- kernel 8: o_pair[i][h][c] = sum_k asum[h][k] pair[i][k][c] ------
__global__ void __launch_bounds__(256) k_opair(const float* __restrict__ pair) {
    __shared__ float ps[2 * 32 * 128];     // [i][k][c]
    __shared__ ull   asumP[12 * 32];       // {a,a} per (h,k)
    int i0 = blockIdx.x * 2;
    int t = threadIdx.x;
    int il = t >> 7;                 // 0/1 (uniform within warp)
    int cg = ((t >> 2) & 31) * 4;    // c base (4 consecutive)
    int h0 = (t & 3) * 3;            // 3 heads

    ull acc[3][2] = {};
    const float4* pair4 = (const float4*)pair;

    for (int k0 = 0; k0 < S; k0 += 32) {
        __syncthreads();
        #pragma unroll
        for (int l = 0; l < 8; l++) {
            int idx = t + l * 256;             // 2048 float4
            int ii = idx >> 10, rem = idx & 1023;
            int k = rem >> 5, c4 = rem & 31;
            float4 v = pair4[((size_t)(i0 + ii) * S + k0 + k) * 32 + c4];
            *(float4*)&ps[(ii * 32 + k) * 128 + c4 * 4] = v;
        }
        for (int idx = t; idx < 384; idx += 256) {
            int h = idx >> 5, k = idx & 31;
            float a = g_asum[h * S + k0 + k];
            ull ad; PACKDUP(ad, a);
            asumP[h * 32 + k] = ad;
        }
        __syncthreads();

        #pragma unroll
        for (int k = 0; k < 32; k++) {
            ulonglong2 p = *(const ulonglong2*)&ps[(il * 32 + k) * 128 + cg];
            ull a0 = asumP[h0 * 32 + k];
            ull a1 = asumP[(h0 + 1) * 32 + k];
            ull a2 = asumP[(h0 + 2) * 32 + k];
            FFMA2(acc[0][0], p.x, a0); FFMA2(acc[0][1], p.y, a0);
            FFMA2(acc[1][0], p.x, a1); FFMA2(acc[1][1], p.y, a1);
            FFMA2(acc[2][0], p.x, a2); FFMA2(acc[2][1], p.y, a2);
        }
    }
    int i = i0 + il;
    #pragma unroll
    for (int hh = 0; hh < 3; hh++) {
        float4 o;
        UNPACK2(o.x, o.y, acc[hh][0]);
        UNPACK2(o.z, o.w, acc[hh][1]);
        *(float4*)&g_attn[i * FOUT + 192 + (h0 + hh) * CP + cg] = o;
    }
}

// ---------------- kernel 9: split-K final GEMM -> partials ----------------
__global__ void __launch_bounds__(256) k_out(const float* __restrict__ Wo) {
    __shared__ float As[32 * 68];   // [kk][m]
    __shared__ float Bs[32 * 68];   // [kk][n]
    int i0 = blockIdx.x * 64, n0 = blockIdx.y * 64;
    int kb = blockIdx.z * (FOUT / SPLITK);
    int ke = kb + (FOUT / SPLITK);
    int t = threadIdx.x, tx = t % 16, ty = t / 16;
    ull acc[4][2] = {};
    for (int kc = kb; kc < ke; kc += 32) {
        __syncthreads();
        for (int idx = t; idx < 64 * 32; idx += 256) {
            int m = idx >> 5, kk = idx & 31;
            As[kk * 68 + m] = g_attn[(i0 + m) * FOUT + kc + kk];
            Bs[kk * 68 + m] = Wo[(n0 + m) * FOUT + kc + kk];
        }
        __syncthreads();
        #pragma unroll 4
        for (int kk = 0; kk < 32; kk++) {
            float4 am = *(const float4*)&As[kk * 68 + ty * 4];
            ulonglong2 bp = *(const ulonglong2*)&Bs[kk * 68 + tx * 4];
            ull a0, a1, a2, a3;
            PACKDUP(a0, am.x); PACKDUP(a1, am.y); PACKDUP(a2, am.z); PACKDUP(a3, am.w);
            FFMA2(acc[0][0], a0, bp.x); FFMA2(acc[0][1], a0, bp.y);
            FFMA2(acc[1][0], a1, bp.x); FFMA2(acc[1][1], a1, bp.y);
            FFMA2(acc[2][0], a2, bp.x); FFMA2(acc[2][1], a2, bp.y);
            FFMA2(acc[3][0], a3, bp.x); FFMA2(acc[3][1], a3, bp.y);
        }
    }
    float* dst = g_part[blockIdx.z];
    #pragma unroll
    for (int r = 0; r < 4; r++) {
        float4 o;
        UNPACK2(o.x, o.y, acc[r][0]);
        UNPACK2(o.z, o.w, acc[r][1]);
        *(float4*)&dst[(i0 + ty * 4 + r) * CS + n0 + tx * 4] = o;
    }
}

__global__ void __launch_bounds__(256) k_fin(const float* __restrict__ bo,
                                             float* __restrict__ out) {
    int idx = blockIdx.x * 256 + threadIdx.x;   // 294912 elems
    int n = idx % CS;
    out[idx] = bo[n] + g_part[0][idx] + g_part[1][idx] + g_part[2][idx];
}

// ---------------- launch (single stream, R4 structure + split asum) ----------------
extern "C" void kernel_launch(void* const* d_in, const int* in_sizes, int n_in,
                              void* d_out, int out_size) {
    const float* single = (const float*)d_in[0];
    const float* pair   = (const float*)d_in[1];
    const float* rot    = (const float*)d_in[2];
    const float* trans  = (const float*)d_in[3];
    const float* Wq     = (const float*)d_in[4];
    const float* Wk     = (const float*)d_in[5];
    const float* Wv     = (const float*)d_in[6];
    const float* Wqp    = (const float*)d_in[7];
    const float* Wkp    = (const float*)d_in[8];
    const float* Wvp    = (const float*)d_in[9];
    const float* Wb     = (const float*)d_in[10];
    const float* Wo     = (const float*)d_in[11];
    const float* bo     = (const float*)d_in[12];
    const float* gamma  = (const float*)d_in[13];
    float* out = (float*)d_out;

    k_proj<<<dim3(S / 8, 2), 288>>>(single, Wq, Wk, Wv, Wqp, Wkp, Wvp);
    k_frames<<<(H * S + 255) / 256, 256>>>(rot, trans, gamma);
    k_logit<<<dim3(S / 64, S / 64, H), 256>>>();
    k_wpair<<<dim3(S, 3), 256>>>(pair, Wb);
    k_softmax<<<S, 384>>>();
    k_asum<<<dim3(S / 256, H, 8), 256>>>();
    k_asred<<<(H * S) / 256, 256>>>();
    k_av<<<dim3(S / 64, H), 256>>>();
    k_invf<<<(H * S + 255) / 256, 256>>>(rot, trans);
    k_opair<<<S / 2, 256>>>(pair);
    k_out<<<dim3(S / 64, CS / 64, SPLITK), 256>>>(Wo);
    k_fin<<<(S * CS) / 256, 256>>>(bo, out);
}

// round 15
// speedup vs baseline: 1.0377x; 1.0055x over previous
#include <cuda_runtime.h>
#include <cuda_bf16.h>
#include <math.h>

#define S   768
#define CS  384
#define CP  128
#define E   16
#define PQ  4
#define PV  8
#define H   12
#define NCOL 1152            // per-residue projection columns: H*96
#define FOUT 2112            // H*(CP+E+PV*4)
#define SPLITK 3

#define SCALE_SINGLE 0.25f   // 1/sqrt(16)
#define SCALE_FRAME (-0.11785113019775793f)   // -1/sqrt(72)

typedef unsigned long long ull;

// packed f32x2 helpers
#define FFMA2(acc, a, b) asm volatile("fma.rn.f32x2 %0, %1, %2, %0;" : "+l"(acc) : "l"(a), "l"(b))
#define PACKDUP(out, x)  asm volatile("mov.b64 %0, {%1, %1};" : "=l"(out) : "f"(x))
#define UNPACK2(lo, hi, v) asm volatile("mov.b64 {%0, %1}, %2;" : "=f"(lo), "=f"(hi) : "l"(v))

// ---------------- scratch ----------------
__device__ float g_raw[S * NCOL];
__device__ float g_Qcat[H * S * 28];
__device__ float g_Kcat[H * S * 28];
__device__ float g_Vcat[H * S * 40];
__device__ float g_qn[H * S];
__device__ float g_kn[H * S];
__device__ float g_a[H * S * S];           // logits -> softmax in place (28.3MB)
__device__ float g_wp[S * H * S];          // pair bias [i][h][j] (28.3MB)
__device__ float g_asum[H * S];
__device__ float g_ol[H * S * PV * 3];
__device__ float g_attn[S * FOUT];
__device__ float g_part[SPLITK][S * CS];

// ---------------- kernel 1: projection GEMM ----------------
__device__ __forceinline__ const float* colptr(int j,
    const float* Wq, const float* Wk, const float* Wv,
    const float* Wqp, const float* Wkp, const float* Wvp) {
    int h = j / 96, off = j % 96;
    if (off < 16) return Wq  + (h * 16 + off) * CS;
    if (off < 32) return Wk  + (h * 16 + off - 16) * CS;
    if (off < 48) return Wv  + (h * 16 + off - 32) * CS;
    if (off < 60) return Wqp + (h * 12 + off - 48) * CS;
    if (off < 72) return Wkp + (h * 12 + off - 60) * CS;
    return Wvp + (h * 24 + off - 72) * CS;
}

// grid (96, 2) x 288 threads: 8 s-rows, 576-column half, exactly 2 cols/thread
__global__ void __launch_bounds__(288) k_proj(const float* __restrict__ x,
    const float* __restrict__ Wq, const float* __restrict__ Wk, const float* __restrict__ Wv,
    const float* __restrict__ Wqp, const float* __restrict__ Wkp, const float* __restrict__ Wvp) {
    __shared__ float xs[8 * CS];
    int s0 = blockIdx.x * 8;
    int j0 = blockIdx.y * 576 + threadIdx.x * 2;
    for (int idx = threadIdx.x; idx < 8 * CS; idx += 288)
        xs[idx] = x[s0 * CS + idx];
    __syncthreads();

    const float* w0 = colptr(j0,     Wq, Wk, Wv, Wqp, Wkp, Wvp);
    const float* w1 = colptr(j0 + 1, Wq, Wk, Wv, Wqp, Wkp, Wvp);
    float acc0[8], acc1[8];
    #pragma unroll
    for (int s = 0; s < 8; s++) { acc0[s] = 0.f; acc1[s] = 0.f; }
    for (int kk = 0; kk < CS; kk += 4) {
        float4 wa = *(const float4*)(w0 + kk);
        float4 wb = *(const float4*)(w1 + kk);
        #pragma unroll
        for (int s = 0; s < 8; s++) {
            float4 xv = *(const float4*)&xs[s * CS + kk];
            acc0[s] += wa.x * xv.x + wa.y * xv.y + wa.z * xv.z + wa.w * xv.w;
            acc1[s] += wb.x * xv.x + wb.y * xv.y + wb.z * xv.z + wb.w * xv.w;
        }
    }
    #pragma unroll
    for (int s = 0; s < 8; s++) {
        g_raw[(s0 + s) * NCOL + j0]     = acc0[s];
        g_raw[(s0 + s) * NCOL + j0 + 1] = acc1[s];
    }
}

// ---------------- kernel 2: frame apply + scale folding ----------------
__global__ void k_frames(const float* __restrict__ rot, const float* __restrict__ trans,
                         const float* __restrict__ gamma) {
    int idx = blockIdx.x * blockDim.x + threadIdx.x;
    if (idx >= H * S) return;
    int h = idx / S, s = idx % S;
    const float* R = rot + s * 9;
    float R00=R[0],R01=R[1],R02=R[2],R10=R[3],R11=R[4],R12=R[5],R20=R[6],R21=R[7],R22=R[8];
    float t0 = trans[s*3+0], t1 = trans[s*3+1], t2 = trans[s*3+2];
    float ch = SCALE_FRAME * log1pf(expf(gamma[h]));

    const float* raw = g_raw + s * NCOL + h * 96;
    float* qc = g_Qcat + (h * S + s) * 28;
    float* kc = g_Kcat + (h * S + s) * 28;
    float* vc = g_Vcat + (h * S + s) * 40;

    #pragma unroll
    for (int e = 0; e < 16; e++) {
        qc[e] = raw[e] * SCALE_SINGLE;
        kc[e] = raw[16 + e];
        vc[e] = raw[32 + e];
    }
    float qn = 0.f, kn = 0.f;
    float m2c = -2.f * ch;
    #pragma unroll
    for (int p = 0; p < 4; p++) {
        float x = raw[48+p*3], y = raw[48+p*3+1], z = raw[48+p*3+2];
        float lx = R00*x + R01*y + R02*z + t0;
        float ly = R10*x + R11*y + R12*z + t1;
        float lz = R20*x + R21*y + R22*z + t2;
        qc[16+p*3]   = lx * m2c;
        qc[16+p*3+1] = ly * m2c;
        qc[16+p*3+2] = lz * m2c;
        qn += lx*lx + ly*ly + lz*lz;

        x = raw[60+p*3]; y = raw[60+p*3+1]; z = raw[60+p*3+2];
        lx = R00*x + R01*y + R02*z + t0;
        ly = R10*x + R11*y + R12*z + t1;
        lz = R20*x + R21*y + R22*z + t2;
        kc[16+p*3]   = lx;
        kc[16+p*3+1] = ly;
        kc[16+p*3+2] = lz;
        kn += lx*lx + ly*ly + lz*lz;
    }
    #pragma unroll
    for (int p = 0; p < 8; p++) {
        float x = raw[72+p*3], y = raw[72+p*3+1], z = raw[72+p*3+2];
        vc[16+p*3]   = R00*x + R01*y + R02*z + t0;
        vc[16+p*3+1] = R10*x + R11*y + R12*z + t1;
        vc[16+p*3+2] = R20*x + R21*y + R22*z + t2;
    }
    g_qn[h * S + s] = ch * qn;
    g_kn[h * S + s] = ch * kn;
}

// ---------------- kernel 3: batched logit GEMM (K=28) ----------------
__global__ void __launch_bounds__(256) k_logit() {
    __shared__ float Qs[64 * 29], Ks[64 * 29], qns[64], kns[64];
    int h = blockIdx.z, i0 = blockIdx.y * 64, j0 = blockIdx.x * 64;
    int t = threadIdx.x;
    for (int idx = t; idx < 64 * 28; idx += 256) {
        int r = idx / 28, c = idx % 28;
        Qs[r * 29 + c] = g_Qcat[(h * S + i0 + r) * 28 + c];
        Ks[r * 29 + c] = g_Kcat[(h * S + j0 + r) * 28 + c];
    }
    if (t < 64) { qns[t] = g_qn[h * S + i0 + t]; kns[t] = g_kn[h * S + j0 + t]; }
    __syncthreads();
    int tx = t % 16, ty = t / 16;
    float acc[4][4] = {};
    for (int k = 0; k < 28; k++) {
        float aq[4], bk[4];
        #pragma unroll
        for (int r = 0; r < 4; r++) {
            aq[r] = Qs[(ty * 4 + r) * 29 + k];
            bk[r] = Ks[(tx * 4 + r) * 29 + k];
        }
        #pragma unroll
        for (int r = 0; r < 4; r++)
            #pragma unroll
            for (int c = 0; c < 4; c++)
                acc[r][c] += aq[r] * bk[c];
    }
    #pragma unroll
    for (int r = 0; r < 4; r++)
        #pragma unroll
        for (int c = 0; c < 4; c++)
            g_a[((size_t)h * S + i0 + ty * 4 + r) * S + j0 + tx * 4 + c] =
                acc[r][c] + qns[ty * 4 + r] + kns[tx * 4 + c];
}

// ---------------- kernel 4a: wp[i][h][j] = Wb[h] . pair[i,j,:] ----------------
// One j per thread; swizzled 128B-row pair tile; Wb via LDS broadcast; K-paired f32x2.
// minBlocksPerMultiprocessor=4 forces <=64 regs -> 4 blocks/SM (was 80 regs, 3 blocks).
__global__ void __launch_bounds__(256, 4) k_wpair(const float* __restrict__ pair,
                                                  const float* __restrict__ Wb) {
    __shared__ float ps[256 * 32];      // [j][32c] swizzled in 16B blocks (32KB)
    __shared__ float wbs[12 * 32];      // Wb chunk [h][32c]
    int i = blockIdx.x, j0 = blockIdx.y * 256;
    int t = threadIdx.x;

    ull acc[12] = {};
    const float4* pair4 = (const float4*)pair;

    for (int c0 = 0; c0 < 128; c0 += 32) {
        __syncthreads();
        #pragma unroll
        for (int l = 0; l < 8; l++) {
            int idx = t + l * 256;            // 2048 float4
            int j = idx >> 3, c4 = idx & 7;
            float4 v = pair4[((size_t)i * S + j0 + j) * 32 + (c0 >> 2) + c4];
            int blk = j * 8 + (c4 ^ (j & 7));
            *(float4*)&ps[blk * 4] = v;
        }
        for (int idx = t; idx < 384; idx += 256)
            wbs[idx] = Wb[(idx >> 5) * CP + c0 + (idx & 31)];
        __syncthreads();

        #pragma unroll
        for (int c4 = 0; c4 < 8; c4++) {
            int blk = t * 8 + (c4 ^ (t & 7));
            ulonglong2 pv = *(const ulonglong2*)&ps[blk * 4];
            #pragma unroll
            for (int h = 0; h < 12; h++) {
                ulonglong2 wb = *(const ulonglong2*)&wbs[h * 32 + c4 * 4];
                FFMA2(acc[h], pv.x, wb.x);
                FFMA2(acc[h], pv.y, wb.y);
            }
        }
    }
    #pragma unroll
    for (int h = 0; h < 12; h++) {
        float lo, hi; UNPACK2(lo, hi, acc[h]);
        g_wp[((size_t)i * H + h) * S + j0 + t] = lo + hi;
    }
}

// ---------------- kernel 4b: softmax over j (adds wp), warp per (head,row) --------
// No smem, no block sync: both g_a row and g_wp row are contiguous.
__global__ void __launch_bounds__(384) k_softmax() {
    int i = blockIdx.x, lane = threadIdx.x & 31, h = threadIdx.x >> 5;

    float4* row = (float4*)(g_a + ((size_t)h * S + i) * S);
    const float4* wr = (const float4*)(g_wp + ((size_t)i * H + h) * S);

    float4 v[6];
    float m = -1e30f;
    #pragma unroll
    for (int r = 0; r < 6; r++) {
        float4 a = row[r * 32 + lane];
        float4 w = wr[r * 32 + lane];
        v[r].x = a.x + w.x; v[r].y = a.y + w.y;
        v[r].z = a.z + w.z; v[r].w = a.w + w.w;
        m = fmaxf(m, fmaxf(fmaxf(v[r].x, v[r].y), fmaxf(v[r].z, v[r].w)));
    }
    #pragma unroll
    for (int off = 16; off; off >>= 1) m = fmaxf(m, __shfl_xor_sync(0xffffffffu, m, off));
    float sum = 0.f;
    #pragma unroll
    for (int r = 0; r < 6; r++) {
        v[r].x = __expf(v[r].x - m); v[r].y = __expf(v[r].y - m);
        v[r].z = __expf(v[r].z - m); v[r].w = __expf(v[r].w - m);
        sum += (v[r].x + v[r].y) + (v[r].z + v[r].w);
    }
    #pragma unroll
    for (int off = 16; off; off >>= 1) sum += __shfl_xor_sync(0xffffffffu, sum, off);
    float inv = 1.f / sum;
    #pragma unroll
    for (int r = 0; r < 6; r++) {
        v[r].x *= inv; v[r].y *= inv; v[r].z *= inv; v[r].w *= inv;
        row[r * 32 + lane] = v[r];
    }
}

// ---------------- kernel 5: a_sum ----------------
__global__ void __launch_bounds__(256) k_asum() {
    int h = blockIdx.y;
    int k = blockIdx.x * 256 + threadIdx.x;
    const float* base = g_a + (size_t)h * S * S + k;
    float s0 = 0.f, s1 = 0.f, s2 = 0.f, s3 = 0.f;
    for (int i = 0; i < S; i += 4) {
        s0 += base[(size_t)(i + 0) * S];
        s1 += base[(size_t)(i + 1) * S];
        s2 += base[(size_t)(i + 2) * S];
        s3 += base[(size_t)(i + 3) * S];
    }
    g_asum[h * S + k] = (s0 + s1) + (s2 + s3);
}

// ---------------- kernel 6: per-head A @ Vcat (256 threads) ----------------
__global__ void __launch_bounds__(256) k_av() {
    __shared__ float As[64 * 65];
    __shared__ float Vs[64 * 41];
    int h = blockIdx.y, i0 = blockIdx.x * 64;
    int t = threadIdx.x;
    int ig = t >> 3, ng = t & 7;     // 32 i-pairs x 8 n-groups
    float acc[2][5] = {};

    for (int kc = 0; kc < S; kc += 64) {
        __syncthreads();
        for (int idx = t; idx < 64 * 64; idx += 256) {
            int r = idx >> 6, k = idx & 63;
            As[r * 65 + k] = g_a[((size_t)h * S + i0 + r) * S + kc + k];
        }
        for (int idx = t; idx < 64 * 40; idx += 256) {
            int r = idx / 40, n = idx % 40;
            Vs[r * 41 + n] = g_Vcat[(h * S + kc + r) * 40 + n];
        }
        __syncthreads();
        #pragma unroll 4
        for (int k = 0; k < 64; k++) {
            float a0 = As[(2 * ig) * 65 + k], a1 = As[(2 * ig + 1) * 65 + k];
            float vv[5];
            #pragma unroll
            for (int c = 0; c < 5; c++) vv[c] = Vs[k * 41 + ng + 8 * c];
            #pragma unroll
            for (int c = 0; c < 5; c++) {
                acc[0][c] += a0 * vv[c];
                acc[1][c] += a1 * vv[c];
            }
        }
    }
    #pragma unroll
    for (int r = 0; r < 2; r++) {
        int i = i0 + 2 * ig + r;
        #pragma unroll
        for (int c = 0; c < 5; c++) {
            int n = ng + 8 * c;
            float val = acc[r][c];
            if (n < 16) g_attn[i * FOUT + h * 16 + n] = val;
            else        g_ol[(h * S + i) * 24 + (n - 16)] = val;
        }
    }
}

// ---------------- kernel 7: inverse frame, points + norms ----------------
__global__ void k_invf(const float* __restrict__ rot, const float* __restrict__ trans) {
    int idx = blockIdx.x * blockDim.x + threadIdx.x;
    if (idx >= H * S) return;
    int h = idx / S, s = idx % S;
    const float* R = rot + s * 9;
    float R00=R[0],R01=R[1],R02=R[2],R10=R[3],R11=R[4],R12=R[5],R20=R[6],R21=R[7],R22=R[8];
    float t0 = trans[s*3+0], t1 = trans[s*3+1], t2 = trans[s*3+2];
    const float* ol = g_ol + (h * S + s) * 24;
    float* dst = g_attn + s * FOUT;
    #pragma unroll
    for (int p = 0; p < PV; p++) {
        float x = ol[p*3+0] - t0, y = ol[p*3+1] - t1, z = ol[p*3+2] - t2;
        float gx = R00*x + R10*y + R20*z;
        float gy = R01*x + R11*y + R21*z;
        float gz = R02*x + R12*y + R22*z;
        dst[1728 + p*36 + h*3 + 0] = gx;
        dst[1728 + p*36 + h*3 + 1] = gy;
        dst[1728 + p*36 + h*3 + 2] = gz;
        dst[2016 + p*12 + h] = sqrtf(gx*gx + gy*gy + gz*gz);
    }
}

// ---------------- kernel 8: o_pair[i][h][c] = sum_k asum[h][k] pair[i][k][c] ------
__global__ void __launch_bounds__(256) k_opair(const float* __restrict__ pair) {
    __shared__ float ps[2 * 32 * 128];     // [i][k][c]
    __shared__ ull   asumP[12 * 32];       // {a,a} per (h,k)
    int i0 = blockIdx.x * 2;
    int t = threadIdx.x;
    int il = t >> 7;                 // 0/1 (uniform within warp)
    int cg = ((t >> 2) & 31) * 4;    // c base (4 consecutive)
    int h0 = (t & 3) * 3;            // 3 heads

    ull acc[3][2] = {};
    const float4* pair4 = (const float4*)pair;

    for (int k0 = 0; k0 < S; k0 += 32) {
        __syncthreads();
        #pragma unroll
        for (int l = 0; l < 8; l++) {
            int idx = t + l * 256;             // 2048 float4
            int ii = idx >> 10, rem = idx & 1023;
            int k = rem >> 5, c4 = rem & 31;
            float4 v = pair4[((size_t)(i0 + ii) * S + k0 + k) * 32 + c4];
            *(float4*)&ps[(ii * 32 + k) * 128 + c4 * 4] = v;
        }
        for (int idx = t; idx < 384; idx += 256) {
            int h = idx >> 5, k = idx & 31;
            float a = g_asum[h * S + k0 + k];
            ull ad; PACKDUP(ad, a);
            asumP[h * 32 + k] = ad;
        }
        __syncthreads();

        #pragma unroll
        for (int k = 0; k < 32; k++) {
            ulonglong2 p = *(const ulonglong2*)&ps[(il * 32 + k) * 128 + cg];
            ull a0 = asumP[h0 * 32 + k];
            ull a1 = asumP[(h0 + 1) * 32 + k];
            ull a2 = asumP[(h0 + 2) * 32 + k];
            FFMA2(acc[0][0], p.x, a0); FFMA2(acc[0][1], p.y, a0);
            FFMA2(acc[1][0], p.x, a1); FFMA2(acc[1][1], p.y, a1);
            FFMA2(acc[2][0], p.x, a2); FFMA2(acc[2][1], p.y, a2);
        }
    }
    int i = i0 + il;
    #pragma unroll
    for (int hh = 0; hh < 3; hh++) {
        float4 o;
        UNPACK2(o.x, o.y, acc[hh][0]);
        UNPACK2(o.z, o.w, acc[hh][1]);
        *(float4*)&g_attn[i * FOUT + 192 + (h0 + hh) * CP + cg] = o;
    }
}

// ---------------- kernel 9: split-K final GEMM -> partials ----------------
__global__ void __launch_bounds__(256) k_out(const float* __restrict__ Wo) {
    __shared__ float As[32 * 68];   // [kk][m]
    __shared__ float Bs[32 * 68];   // [kk][n]
    int i0 = blockIdx.x * 64, n0 = blockIdx.y * 64;
    int kb = blockIdx.z * (FOUT / SPLITK);
    int ke = kb + (FOUT / SPLITK);
    int t = threadIdx.x, tx = t % 16, ty = t / 16;
    ull acc[4][2] = {};
    for (int kc = kb; kc < ke; kc += 32) {
        __syncthreads();
        for (int idx = t; idx < 64 * 32; idx += 256) {
            int m = idx >> 5, kk = idx & 31;
            As[kk * 68 + m] = g_attn[(i0 + m) * FOUT + kc + kk];
            Bs[kk * 68 + m] = Wo[(n0 + m) * FOUT + kc + kk];
        }
        __syncthreads();
        #pragma unroll 4
        for (int kk = 0; kk < 32; kk++) {
            float4 am = *(const float4*)&As[kk * 68 + ty * 4];
            ulonglong2 bp = *(const ulonglong2*)&Bs[kk * 68 + tx * 4];
            ull a0, a1, a2, a3;
            PACKDUP(a0, am.x); PACKDUP(a1, am.y); PACKDUP(a2, am.z); PACKDUP(a3, am.w);
            FFMA2(acc[0][0], a0, bp.x); FFMA2(acc[0][1], a0, bp.y);
            FFMA2(acc[1][0], a1, bp.x); FFMA2(acc[1][1], a1, bp.y);
            FFMA2(acc[2][0], a2, bp.x); FFMA2(acc[2][1], a2, bp.y);
            FFMA2(acc[3][0], a3, bp.x); FFMA2(acc[3][1], a3, bp.y);
        }
    }
    float* dst = g_part[blockIdx.z];
    #pragma unroll
    for (int r = 0; r < 4; r++) {
        float4 o;
        UNPACK2(o.x, o.y, acc[r][0]);
        UNPACK2(o.z, o.w, acc[r][1]);
        *(float4*)&dst[(i0 + ty * 4 + r) * CS + n0 + tx * 4] = o;
    }
}

__global__ void __launch_bounds__(256) k_fin(const float* __restrict__ bo,
                                             float* __restrict__ out) {
    int idx = blockIdx.x * 256 + threadIdx.x;   // 294912 elems
    int n = idx % CS;
    out[idx] = bo[n] + g_part[0][idx] + g_part[1][idx] + g_part[2][idx];
}

// ---------------- launch (exact R4 structure; only k_wpair launch_bounds changed) --
extern "C" void kernel_launch(void* const* d_in, const int* in_sizes, int n_in,
                              void* d_out, int out_size) {
    const float* single = (const float*)d_in[0];
    const float* pair   = (const float*)d_in[1];
    const float* rot    = (const float*)d_in[2];
    const float* trans  = (const float*)d_in[3];
    const float* Wq     = (const float*)d_in[4];
    const float* Wk     = (const float*)d_in[5];
    const float* Wv     = (const float*)d_in[6];
    const float* Wqp    = (const float*)d_in[7];
    const float* Wkp    = (const float*)d_in[8];
    const float* Wvp    = (const float*)d_in[9];
    const float* Wb     = (const float*)d_in[10];
    const float* Wo     = (const float*)d_in[11];
    const float* bo     = (const float*)d_in[12];
    const float* gamma  = (const float*)d_in[13];
    float* out = (float*)d_out;

    k_proj<<<dim3(S / 8, 2), 288>>>(single, Wq, Wk, Wv, Wqp, Wkp, Wvp);
    k_frames<<<(H * S + 255) / 256, 256>>>(rot, trans, gamma);
    k_logit<<<dim3(S / 64, S / 64, H), 256>>>();
    k_wpair<<<dim3(S, 3), 256>>>(pair, Wb);
    k_softmax<<<S, 384>>>();
    k_asum<<<dim3(S / 256, H), 256>>>();
    k_av<<<dim3(S / 64, H), 256>>>();
    k_invf<<<(H * S + 255) / 256, 256>>>(rot, trans);
    k_opair<<<S / 2, 256>>>(pair);
    k_out<<<dim3(S / 64, CS / 64, SPLITK), 256>>>(Wo);
    k_fin<<<(S * CS) / 256, 256>>>(bo, out);
}